// round 3
// baseline (speedup 1.0000x reference)
#include <cuda_runtime.h>

#define D_FEAT 64
#define MAX_NODES 100000

// Scratch: CSR-style row pointer, rebuilt deterministically every launch.
__device__ int g_row_ptr[MAX_NODES + 1];

// Build row_ptr from the sorted target index: row_ptr[v] = first edge e with
// tgt[e] >= v. Boundary ranges are disjoint across e -> race-free writes.
__global__ void build_row_ptr_kernel(const int* __restrict__ tgt,
                                     int n_edges, int n_nodes) {
    const int e = blockIdx.x * blockDim.x + threadIdx.x;
    if (e >= n_edges) return;
    const int cur  = __ldg(tgt + e);
    const int prev = (e == 0) ? -1 : __ldg(tgt + e - 1);
    for (int v = prev + 1; v <= cur; ++v) g_row_ptr[v] = e;
    if (e == n_edges - 1) {
        for (int v = cur + 1; v <= n_nodes; ++v) g_row_ptr[v] = n_edges;
    }
}

// One warp per output node. Half-warp h (lanes 16h..16h+15) serves edges with
// parity h; lane owns a float4 feature chunk. Main loop processes 4 edge-PAIRS
// per iteration => 4 independent float4 gathers in flight per lane (8/warp).
__global__ __launch_bounds__(256) void mp_gather_kernel(
    const float* __restrict__ x,    // [n_nodes, 64]
    const float* __restrict__ ev,   // [n_edges]
    const int*   __restrict__ src,  // [n_edges]
    float*       __restrict__ out,  // [n_nodes, 64]
    int n_nodes)
{
    const int warp = (blockIdx.x * blockDim.x + threadIdx.x) >> 5;
    if (warp >= n_nodes) return;
    const int lane = threadIdx.x & 31;
    const int half = lane >> 4;
    const int hl   = lane & 15;
    const int node = warp;

    const int start = __ldg(&g_row_ptr[node]);
    const int end   = __ldg(&g_row_ptr[node + 1]);

    const float4* __restrict__ xf4 = (const float4*)x;
    float4 acc = make_float4(0.f, 0.f, 0.f, 0.f);

    for (int base = start; base < end; base += 32) {
        const int cnt = min(32, end - base);
        // Cooperative metadata load: lane l owns edge base+l of this batch.
        int   s_l = 0;
        float w_l = 0.f;
        if (lane < cnt) {
            s_l = __ldg(src + base + lane);
            w_l = __ldg(ev  + base + lane);
        }

        const int full = cnt >> 1;   // complete edge pairs (both parities valid)
        int k = 0;

        // --- main path: 4 pairs/iter -> 4 independent gathers per lane ---
        for (; k + 4 <= full; k += 4) {
            const int j0 = 2 * (k + 0) + half;
            const int j1 = 2 * (k + 1) + half;
            const int j2 = 2 * (k + 2) + half;
            const int j3 = 2 * (k + 3) + half;
            const int   s0 = __shfl_sync(0xffffffffu, s_l, j0);
            const int   s1 = __shfl_sync(0xffffffffu, s_l, j1);
            const int   s2 = __shfl_sync(0xffffffffu, s_l, j2);
            const int   s3 = __shfl_sync(0xffffffffu, s_l, j3);
            const float w0 = __shfl_sync(0xffffffffu, w_l, j0);
            const float w1 = __shfl_sync(0xffffffffu, w_l, j1);
            const float w2 = __shfl_sync(0xffffffffu, w_l, j2);
            const float w3 = __shfl_sync(0xffffffffu, w_l, j3);
            const float4 v0 = __ldg(&xf4[(size_t)s0 * 16 + hl]);
            const float4 v1 = __ldg(&xf4[(size_t)s1 * 16 + hl]);
            const float4 v2 = __ldg(&xf4[(size_t)s2 * 16 + hl]);
            const float4 v3 = __ldg(&xf4[(size_t)s3 * 16 + hl]);
            acc.x = fmaf(w0, v0.x, acc.x); acc.y = fmaf(w0, v0.y, acc.y);
            acc.z = fmaf(w0, v0.z, acc.z); acc.w = fmaf(w0, v0.w, acc.w);
            acc.x = fmaf(w1, v1.x, acc.x); acc.y = fmaf(w1, v1.y, acc.y);
            acc.z = fmaf(w1, v1.z, acc.z); acc.w = fmaf(w1, v1.w, acc.w);
            acc.x = fmaf(w2, v2.x, acc.x); acc.y = fmaf(w2, v2.y, acc.y);
            acc.z = fmaf(w2, v2.z, acc.z); acc.w = fmaf(w2, v2.w, acc.w);
            acc.x = fmaf(w3, v3.x, acc.x); acc.y = fmaf(w3, v3.y, acc.y);
            acc.z = fmaf(w3, v3.z, acc.z); acc.w = fmaf(w3, v3.w, acc.w);
        }
        // --- remaining complete pairs ---
        for (; k < full; ++k) {
            const int j = 2 * k + half;
            const int   s = __shfl_sync(0xffffffffu, s_l, j);
            const float w = __shfl_sync(0xffffffffu, w_l, j);
            const float4 v = __ldg(&xf4[(size_t)s * 16 + hl]);
            acc.x = fmaf(w, v.x, acc.x); acc.y = fmaf(w, v.y, acc.y);
            acc.z = fmaf(w, v.z, acc.z); acc.w = fmaf(w, v.w, acc.w);
        }
        // --- odd trailing edge: processed by half 0 only ---
        if (cnt & 1) {
            const int j = cnt - 1;
            const int   s = __shfl_sync(0xffffffffu, s_l, j);
            float       w = __shfl_sync(0xffffffffu, w_l, j);
            if (half) w = 0.f;  // half 1 contributes zero (load is still valid)
            const float4 v = __ldg(&xf4[(size_t)s * 16 + hl]);
            acc.x = fmaf(w, v.x, acc.x); acc.y = fmaf(w, v.y, acc.y);
            acc.z = fmaf(w, v.z, acc.z); acc.w = fmaf(w, v.w, acc.w);
        }
    }

    // Combine the two half-warp partial sums.
    acc.x += __shfl_xor_sync(0xffffffffu, acc.x, 16);
    acc.y += __shfl_xor_sync(0xffffffffu, acc.y, 16);
    acc.z += __shfl_xor_sync(0xffffffffu, acc.z, 16);
    acc.w += __shfl_xor_sync(0xffffffffu, acc.w, 16);

    if (half == 0) {
        float4* __restrict__ of4 = (float4*)out;
        of4[(size_t)node * 16 + hl] = acc;  // 256B coalesced store
    }
}

extern "C" void kernel_launch(void* const* d_in, const int* in_sizes, int n_in,
                              void* d_out, int out_size) {
    const float* x   = (const float*)d_in[0];
    const float* ev  = (const float*)d_in[1];
    const int*   tgt = (const int*)d_in[2];
    const int*   src = (const int*)d_in[3];
    float* out = (float*)d_out;

    const int n_edges = in_sizes[1];
    const int n_nodes = out_size / D_FEAT;

    {
        const int threads = 256;
        const int blocks  = (n_edges + threads - 1) / threads;
        build_row_ptr_kernel<<<blocks, threads>>>(tgt, n_edges, n_nodes);
    }
    {
        const int threads = 256;
        const int blocks  = (n_nodes * 32 + threads - 1) / threads;
        mp_gather_kernel<<<blocks, threads>>>(x, ev, src, out, n_nodes);
    }
}